// round 1
// baseline (speedup 1.0000x reference)
#include <cuda_runtime.h>

// Problem: x[16384, 32] fp32 -> out[i,j] = ||x[i]-x[j]||_2, [16384,16384] fp32.
// GEMM-formula: d2 = ||xi||^2 + ||xj||^2 - 2 xi.xj, clamp, sqrt.
// 128x128 tile per CTA, 256 threads, 8x8 outputs/thread, packed fma.rn.f32x2.

#define NPTS 16384

__device__ __forceinline__ unsigned long long pack_dup(float v) {
    unsigned long long r;
    asm("mov.b64 %0, {%1, %1};" : "=l"(r) : "f"(v));
    return r;
}
__device__ __forceinline__ unsigned long long fma_f32x2(
    unsigned long long a, unsigned long long b, unsigned long long c) {
    unsigned long long d;
    asm("fma.rn.f32x2 %0, %1, %2, %3;" : "=l"(d) : "l"(a), "l"(b), "l"(c));
    return d;
}
__device__ __forceinline__ float2 unpack2(unsigned long long v) {
    float2 f;
    asm("mov.b64 {%0, %1}, %2;" : "=f"(f.x), "=f"(f.y) : "l"(v));
    return f;
}
__device__ __forceinline__ unsigned long long lds_b64(const float* p) {
    unsigned long long r;
    unsigned a = (unsigned)__cvta_generic_to_shared(p);
    asm("ld.shared.b64 %0, [%1];" : "=l"(r) : "r"(a));
    return r;
}
__device__ __forceinline__ float sqrt_approx(float x) {
    float r;
    asm("sqrt.approx.f32 %0, %1;" : "=f"(r) : "f"(x));
    return r;
}
__device__ __forceinline__ float dist_val(float si, float sj, float dot) {
    float d2 = fmaxf(fmaf(-2.0f, dot, si + sj), 0.0f);
    return sqrt_approx(d2);
}

__global__ void __launch_bounds__(256, 2)
cdist_tile_kernel(const float* __restrict__ x, float* __restrict__ out)
{
    // A: k-major, pad 130 -> ld.shared.b64 of adjacent rows is 8B aligned,
    //    and the transposed STS during load is only 2-way conflicted.
    // B: k-major, pad 132 -> float4 reads are 16B aligned.
    __shared__ float A_s[32][130];
    __shared__ float B_s[32][132];
    __shared__ float sqa[128];
    __shared__ float sqb[128];

    const int t  = threadIdx.x;
    const int a0 = blockIdx.y << 7;  // tile row base
    const int b0 = blockIdx.x << 7;  // tile col base

    // ---- Load both 128x32 tiles (transposed to k-major in smem) ----
    const float4* xv = (const float4*)x;  // x row = 8 float4
    #pragma unroll
    for (int i = 0; i < 4; i++) {
        int q   = i * 256 + t;   // 0..1023
        int row = q >> 3;
        int kq  = q & 7;
        float4 va = xv[((size_t)(a0 + row) << 3) + kq];
        float4 vb = xv[((size_t)(b0 + row) << 3) + kq];
        int k = kq << 2;
        A_s[k + 0][row] = va.x; A_s[k + 1][row] = va.y;
        A_s[k + 2][row] = va.z; A_s[k + 3][row] = va.w;
        B_s[k + 0][row] = vb.x; B_s[k + 1][row] = vb.y;
        B_s[k + 2][row] = vb.z; B_s[k + 3][row] = vb.w;
    }
    __syncthreads();

    // ---- Per-row squared norms ----
    if (t < 128) {
        float s = 0.0f;
        #pragma unroll
        for (int k = 0; k < 32; k++) s = fmaf(A_s[k][t], A_s[k][t], s);
        sqa[t] = s;
    } else {
        int r = t - 128;
        float s = 0.0f;
        #pragma unroll
        for (int k = 0; k < 32; k++) s = fmaf(B_s[k][r], B_s[k][r], s);
        sqb[r] = s;
    }
    __syncthreads();

    // ---- Register-tiled GEMM: rows paired in f32x2 lanes ----
    const int tx    = t & 15;
    const int ty    = t >> 4;
    const int rbase = ty << 3;       // 8 rows: rbase..rbase+7
    const int cb0   = tx << 2;       // cols cb0..cb0+3
    const int cb1   = 64 + cb0;      // cols cb1..cb1+3

    unsigned long long acc[4][8];
    #pragma unroll
    for (int rp = 0; rp < 4; rp++)
        #pragma unroll
        for (int c = 0; c < 8; c++) acc[rp][c] = 0ULL;

    #pragma unroll
    for (int k = 0; k < 32; k++) {
        unsigned long long a2[4];
        #pragma unroll
        for (int rp = 0; rp < 4; rp++)
            a2[rp] = lds_b64(&A_s[k][rbase + (rp << 1)]);  // (row, row+1)

        float4 bv0 = *(const float4*)&B_s[k][cb0];
        float4 bv1 = *(const float4*)&B_s[k][cb1];
        unsigned long long bb[8];
        bb[0] = pack_dup(bv0.x); bb[1] = pack_dup(bv0.y);
        bb[2] = pack_dup(bv0.z); bb[3] = pack_dup(bv0.w);
        bb[4] = pack_dup(bv1.x); bb[5] = pack_dup(bv1.y);
        bb[6] = pack_dup(bv1.z); bb[7] = pack_dup(bv1.w);

        #pragma unroll
        for (int rp = 0; rp < 4; rp++)
            #pragma unroll
            for (int c = 0; c < 8; c++)
                acc[rp][c] = fma_f32x2(a2[rp], bb[c], acc[rp][c]);
    }

    // ---- Epilogue: d = sqrt(max(si + sj - 2*dot, 0)), coalesced float4 STG ----
    float sj0[4], sj1[4];
    #pragma unroll
    for (int c = 0; c < 4; c++) { sj0[c] = sqb[cb0 + c]; sj1[c] = sqb[cb1 + c]; }

    #pragma unroll
    for (int rp = 0; rp < 4; rp++) {
        int lrow = rbase + (rp << 1);
        float si0 = sqa[lrow];
        float si1 = sqa[lrow + 1];

        float2 d[8];
        #pragma unroll
        for (int c = 0; c < 8; c++) d[c] = unpack2(acc[rp][c]);

        size_t gi = (size_t)(a0 + lrow);
        float* r0 = out + (gi << 14) + b0;
        float* r1 = out + ((gi + 1) << 14) + b0;

        float4 w;
        w.x = dist_val(si0, sj0[0], d[0].x);
        w.y = dist_val(si0, sj0[1], d[1].x);
        w.z = dist_val(si0, sj0[2], d[2].x);
        w.w = dist_val(si0, sj0[3], d[3].x);
        *(float4*)(r0 + cb0) = w;
        w.x = dist_val(si0, sj1[0], d[4].x);
        w.y = dist_val(si0, sj1[1], d[5].x);
        w.z = dist_val(si0, sj1[2], d[6].x);
        w.w = dist_val(si0, sj1[3], d[7].x);
        *(float4*)(r0 + cb1) = w;

        w.x = dist_val(si1, sj0[0], d[0].y);
        w.y = dist_val(si1, sj0[1], d[1].y);
        w.z = dist_val(si1, sj0[2], d[2].y);
        w.w = dist_val(si1, sj0[3], d[3].y);
        *(float4*)(r1 + cb0) = w;
        w.x = dist_val(si1, sj1[0], d[4].y);
        w.y = dist_val(si1, sj1[1], d[5].y);
        w.z = dist_val(si1, sj1[2], d[6].y);
        w.w = dist_val(si1, sj1[3], d[7].y);
        *(float4*)(r1 + cb1) = w;
    }
}

extern "C" void kernel_launch(void* const* d_in, const int* in_sizes, int n_in,
                              void* d_out, int out_size)
{
    (void)in_sizes; (void)n_in; (void)out_size;
    const float* x = (const float*)d_in[0];
    float* out = (float*)d_out;
    dim3 grid(NPTS / 128, NPTS / 128);  // (128, 128) tiles
    dim3 block(256);
    cdist_tile_kernel<<<grid, block>>>(x, out);
}

// round 3
// speedup vs baseline: 1.1900x; 1.1900x over previous
#include <cuda_runtime.h>
#include <cuda_bf16.h>
#include <stdint.h>

// cdist: out[i,j] = sqrt(max(||xi||^2 + ||xj||^2 - 2*dot(xi,xj), 0))
// dot via bf16 hi/lo split on mma.sync (portable HMMA, no sm_103a-only PTX):
//   dot ~= hiA.hiB + hiA.loB + loA.hiB   (3 passes of K=32)
// CTA: 128x128 tile, 256 thr, 8 warps (2x4), warp tile 64x32 (4x4 m16n8k16).

#define NPTS 16384

__device__ __forceinline__ float sqrt_approx(float v) {
    float r; asm("sqrt.approx.f32 %0, %1;" : "=f"(r) : "f"(v)); return r;
}
__device__ __forceinline__ float dist_val(float si, float sj, float dot) {
    return sqrt_approx(fmaxf(fmaf(-2.0f, dot, si + sj), 0.0f));
}
__device__ __forceinline__ uint32_t smem_u32(const void* p) {
    return (uint32_t)__cvta_generic_to_shared(p);
}
__device__ __forceinline__ void ldmatrix_x4(uint32_t* r, uint32_t addr) {
    asm volatile("ldmatrix.sync.aligned.m8n8.x4.shared.b16 {%0,%1,%2,%3}, [%4];"
                 : "=r"(r[0]), "=r"(r[1]), "=r"(r[2]), "=r"(r[3]) : "r"(addr));
}
__device__ __forceinline__ void ldmatrix_x2(uint32_t* r, uint32_t addr) {
    asm volatile("ldmatrix.sync.aligned.m8n8.x2.shared.b16 {%0,%1}, [%2];"
                 : "=r"(r[0]), "=r"(r[1]) : "r"(addr));
}
__device__ __forceinline__ void mma_bf16(float* c, const uint32_t* a, const uint32_t* b) {
    asm volatile(
        "mma.sync.aligned.m16n8k16.row.col.f32.bf16.bf16.f32 "
        "{%0,%1,%2,%3}, {%4,%5,%6,%7}, {%8,%9}, {%0,%1,%2,%3};"
        : "+f"(c[0]), "+f"(c[1]), "+f"(c[2]), "+f"(c[3])
        : "r"(a[0]), "r"(a[1]), "r"(a[2]), "r"(a[3]), "r"(b[0]), "r"(b[1]));
}

// 16B store into SW128-swizzled [128][128B] tile
__device__ __forceinline__ void st16_sw(uint8_t* buf, uint32_t off, uint4 v) {
    off ^= (off >> 3) & 0x70;
    *(uint4*)(buf + off) = v;
}

// Convert half a row (16 floats) to hi/lo bf16, store swizzled; return sumsq.
__device__ __forceinline__ float cvt_store(uint8_t* __restrict__ buf, int row,
                                           int half, const float4* __restrict__ src)
{
    float s = 0.0f;
    uint32_t H[8], L[8];
#pragma unroll
    for (int q = 0; q < 4; q++) {
        float4 v = src[q];
        s = fmaf(v.x, v.x, s); s = fmaf(v.y, v.y, s);
        s = fmaf(v.z, v.z, s); s = fmaf(v.w, v.w, s);
        __nv_bfloat16 hx = __float2bfloat16_rn(v.x);
        __nv_bfloat16 hy = __float2bfloat16_rn(v.y);
        __nv_bfloat16 hz = __float2bfloat16_rn(v.z);
        __nv_bfloat16 hw = __float2bfloat16_rn(v.w);
        __nv_bfloat162 h01 = __halves2bfloat162(hx, hy);
        __nv_bfloat162 h23 = __halves2bfloat162(hz, hw);
        __nv_bfloat162 l01 = __floats2bfloat162_rn(v.x - __bfloat162float(hx),
                                                   v.y - __bfloat162float(hy));
        __nv_bfloat162 l23 = __floats2bfloat162_rn(v.z - __bfloat162float(hz),
                                                   v.w - __bfloat162float(hw));
        H[q * 2 + 0] = *(uint32_t*)&h01; H[q * 2 + 1] = *(uint32_t*)&h23;
        L[q * 2 + 0] = *(uint32_t*)&l01; L[q * 2 + 1] = *(uint32_t*)&l23;
    }
    // hi at bf16 cols [half*16 .. half*16+15] -> bytes row*128 + half*32
    // lo at bf16 cols [32+half*16 ..]        -> bytes row*128 + 64 + half*32
    uint32_t base = (uint32_t)row * 128 + (uint32_t)half * 32;
    st16_sw(buf, base +  0, make_uint4(H[0], H[1], H[2], H[3]));
    st16_sw(buf, base + 16, make_uint4(H[4], H[5], H[6], H[7]));
    st16_sw(buf, base + 64, make_uint4(L[0], L[1], L[2], L[3]));
    st16_sw(buf, base + 80, make_uint4(L[4], L[5], L[6], L[7]));
    return s;
}

__global__ void __launch_bounds__(256, 2)
cdist_mma_kernel(const float* __restrict__ x, float* __restrict__ out)
{
    __shared__ __align__(128) uint8_t Abuf[128 * 128];
    __shared__ __align__(128) uint8_t Bbuf[128 * 128];
    __shared__ float sqa[128];
    __shared__ float sqb[128];

    const int t    = threadIdx.x;
    const int lane = t & 31;
    const int wid  = t >> 5;
    const int a0   = blockIdx.y << 7;
    const int b0   = blockIdx.x << 7;

    // ---- load + hi/lo convert (thread t: row t/2, half t&1) ----
    {
        const int row  = t >> 1;
        const int half = t & 1;
        const float4* xa = (const float4*)(x + ((size_t)(a0 + row) << 5)) + half * 4;
        const float4* xb = (const float4*)(x + ((size_t)(b0 + row) << 5)) + half * 4;
        float sa = cvt_store(Abuf, row, half, xa);
        float sb = cvt_store(Bbuf, row, half, xb);
        sa += __shfl_xor_sync(0xFFFFFFFFu, sa, 1);
        sb += __shfl_xor_sync(0xFFFFFFFFu, sb, 1);
        if (!half) { sqa[row] = sa; sqb[row] = sb; }
    }
    __syncthreads();

    // ---- warp GEMM ----
    const int wr = wid >> 2;   // 0..1 (row group of 64)
    const int wc = wid & 3;    // 0..3 (col group of 32)

    const uint32_t aBase  = smem_u32(Abuf) + (uint32_t)(wr * 64 + (lane & 15)) * 128;
    const uint32_t aXmask = (uint32_t)(lane & 7) << 4;
    const uint32_t aKhalf = (uint32_t)(lane >> 4) << 4;          // +16B for lanes>=16
    const uint32_t bBase  = smem_u32(Bbuf) + (uint32_t)(wc * 32 + (lane & 7)) * 128;
    const uint32_t bXmask = aXmask;
    const uint32_t bKhalf = (uint32_t)((lane >> 3) & 1) << 4;    // +16B for lanes 8-15

    float acc[4][4][4];
#pragma unroll
    for (int mt = 0; mt < 4; mt++)
#pragma unroll
        for (int nt = 0; nt < 4; nt++)
#pragma unroll
            for (int i = 0; i < 4; i++) acc[mt][nt][i] = 0.0f;

    const int passA[3] = {0, 0, 64};   // byte col: hi=0, lo=64
    const int passB[3] = {0, 64, 0};
#pragma unroll
    for (int p = 0; p < 3; p++) {
#pragma unroll
        for (int ks = 0; ks < 2; ks++) {
            const uint32_t kbA = (uint32_t)(passA[p] + ks * 32) + aKhalf;
            const uint32_t kbB = (uint32_t)(passB[p] + ks * 32) + bKhalf;
            uint32_t af[4][4], bf[4][2];
#pragma unroll
            for (int mt = 0; mt < 4; mt++)
                ldmatrix_x4(af[mt], aBase + (uint32_t)mt * 2048 + (kbA ^ aXmask));
#pragma unroll
            for (int nt = 0; nt < 4; nt++)
                ldmatrix_x2(bf[nt], bBase + (uint32_t)nt * 1024 + (kbB ^ bXmask));
#pragma unroll
            for (int mt = 0; mt < 4; mt++)
#pragma unroll
                for (int nt = 0; nt < 4; nt++)
                    mma_bf16(acc[mt][nt], af[mt], bf[nt]);
        }
    }

    // ---- epilogue ----
    const int gr = lane >> 2;            // 0..7
    const int tc = (lane & 3) << 1;      // 0,2,4,6
    const bool diag = (a0 == b0);
#pragma unroll
    for (int mt = 0; mt < 4; mt++) {
        const int r0l = wr * 64 + mt * 16 + gr;
        const int r1l = r0l + 8;
        const float si0 = sqa[r0l], si1 = sqa[r1l];
        const int g0 = a0 + r0l, g1 = a0 + r1l;
        float* __restrict__ o0 = out + ((size_t)g0 << 14);
        float* __restrict__ o1 = out + ((size_t)g1 << 14);
#pragma unroll
        for (int nt = 0; nt < 4; nt++) {
            const int cl = wc * 32 + nt * 8 + tc;
            const int gc = b0 + cl;
            const float sj0 = sqb[cl], sj1 = sqb[cl + 1];
            float2 w0, w1;
            w0.x = dist_val(si0, sj0, acc[mt][nt][0]);
            w0.y = dist_val(si0, sj1, acc[mt][nt][1]);
            w1.x = dist_val(si1, sj0, acc[mt][nt][2]);
            w1.y = dist_val(si1, sj1, acc[mt][nt][3]);
            if (diag) {
                if (g0 == gc)     w0.x = 0.0f;
                if (g0 == gc + 1) w0.y = 0.0f;
                if (g1 == gc)     w1.x = 0.0f;
                if (g1 == gc + 1) w1.y = 0.0f;
            }
            *(float2*)(o0 + gc) = w0;
            *(float2*)(o1 + gc) = w1;
        }
    }
}

extern "C" void kernel_launch(void* const* d_in, const int* in_sizes, int n_in,
                              void* d_out, int out_size)
{
    (void)in_sizes; (void)n_in; (void)out_size;
    const float* x = (const float*)d_in[0];
    float* out = (float*)d_out;
    dim3 grid(NPTS / 128, NPTS / 128);
    dim3 block(256);
    cdist_mma_kernel<<<grid, block>>>(x, out);
}

// round 4
// speedup vs baseline: 1.4955x; 1.2567x over previous
#include <cuda_runtime.h>
#include <cuda_bf16.h>
#include <stdint.h>

// cdist: out[i,j] = sqrt(max(||xi||^2 + ||xj||^2 - 2*dot(xi,xj), 0))
// dot via bf16 hi/lo split on mma.sync: dot ~= hiA.hiB + hiA.loB + loA.hiB.
// R4: frag reuse across hi/lo passes, B via ldmatrix.x4, STG.128 epilogue
// through a B-column permutation.

#define NPTS 16384

__device__ __forceinline__ float sqrt_approx(float v) {
    float r; asm("sqrt.approx.f32 %0, %1;" : "=f"(r) : "f"(v)); return r;
}
__device__ __forceinline__ float dist_val(float si, float sj, float dot) {
    return sqrt_approx(fmaxf(fmaf(-2.0f, dot, si + sj), 0.0f));
}
__device__ __forceinline__ uint32_t smem_u32(const void* p) {
    return (uint32_t)__cvta_generic_to_shared(p);
}
__device__ __forceinline__ void ldmatrix_x4(uint32_t* r, uint32_t addr) {
    asm volatile("ldmatrix.sync.aligned.m8n8.x4.shared.b16 {%0,%1,%2,%3}, [%4];"
                 : "=r"(r[0]), "=r"(r[1]), "=r"(r[2]), "=r"(r[3]) : "r"(addr));
}
__device__ __forceinline__ void mma_bf16(float* c, const uint32_t* a, const uint32_t* b) {
    asm volatile(
        "mma.sync.aligned.m16n8k16.row.col.f32.bf16.bf16.f32 "
        "{%0,%1,%2,%3}, {%4,%5,%6,%7}, {%8,%9}, {%0,%1,%2,%3};"
        : "+f"(c[0]), "+f"(c[1]), "+f"(c[2]), "+f"(c[3])
        : "r"(a[0]), "r"(a[1]), "r"(a[2]), "r"(a[3]), "r"(b[0]), "r"(b[1]));
}

// 16B store into SW128-swizzled [128][128B] tile
__device__ __forceinline__ void st16_sw(uint8_t* buf, uint32_t off, uint4 v) {
    off ^= (off >> 3) & 0x70;
    *(uint4*)(buf + off) = v;
}

// Convert half a row (16 floats) to hi/lo bf16, store swizzled; return sumsq.
__device__ __forceinline__ float cvt_store(uint8_t* __restrict__ buf, int row,
                                           int half, const float4* __restrict__ src)
{
    float s = 0.0f;
    uint32_t H[8], L[8];
#pragma unroll
    for (int q = 0; q < 4; q++) {
        float4 v = src[q];
        s = fmaf(v.x, v.x, s); s = fmaf(v.y, v.y, s);
        s = fmaf(v.z, v.z, s); s = fmaf(v.w, v.w, s);
        __nv_bfloat16 hx = __float2bfloat16_rn(v.x);
        __nv_bfloat16 hy = __float2bfloat16_rn(v.y);
        __nv_bfloat16 hz = __float2bfloat16_rn(v.z);
        __nv_bfloat16 hw = __float2bfloat16_rn(v.w);
        __nv_bfloat162 h01 = __halves2bfloat162(hx, hy);
        __nv_bfloat162 h23 = __halves2bfloat162(hz, hw);
        __nv_bfloat162 l01 = __floats2bfloat162_rn(v.x - __bfloat162float(hx),
                                                   v.y - __bfloat162float(hy));
        __nv_bfloat162 l23 = __floats2bfloat162_rn(v.z - __bfloat162float(hz),
                                                   v.w - __bfloat162float(hw));
        H[q * 2 + 0] = *(uint32_t*)&h01; H[q * 2 + 1] = *(uint32_t*)&h23;
        L[q * 2 + 0] = *(uint32_t*)&l01; L[q * 2 + 1] = *(uint32_t*)&l23;
    }
    uint32_t base = (uint32_t)row * 128 + (uint32_t)half * 32;
    st16_sw(buf, base +  0, make_uint4(H[0], H[1], H[2], H[3]));
    st16_sw(buf, base + 16, make_uint4(H[4], H[5], H[6], H[7]));
    st16_sw(buf, base + 64, make_uint4(L[0], L[1], L[2], L[3]));
    st16_sw(buf, base + 80, make_uint4(L[4], L[5], L[6], L[7]));
    return s;
}

__global__ void __launch_bounds__(256, 2)
cdist_mma_kernel(const float* __restrict__ x, float* __restrict__ out)
{
    __shared__ __align__(128) uint8_t Abuf[128 * 128];
    __shared__ __align__(128) uint8_t Bbuf[128 * 128];
    __shared__ float sqa[128];
    __shared__ float sqb[128];

    const int t    = threadIdx.x;
    const int lane = t & 31;
    const int wid  = t >> 5;
    const int a0   = blockIdx.y << 7;
    const int b0   = blockIdx.x << 7;

    // ---- load + hi/lo convert (thread t: row t/2, half t&1) ----
    // B rows permuted within each 16-group so each epilogue thread's 4
    // accumulator columns are globally contiguous:
    //   perm[v] (smem pos -> global):  [0,1,4,5,8,9,12,13,2,3,6,7,10,11,14,15]
    //   invperm (global v -> smem pos): ((w&1)<<3)|((w>>1)<<1)|r, w=v>>1, r=v&1
    {
        const int row  = t >> 1;
        const int half = t & 1;
        const int v = row & 15, w = v >> 1, r = v & 1;
        const int srowB = (row & ~15) | ((w & 1) << 3) | ((w >> 1) << 1) | r;
        const float4* xa = (const float4*)(x + ((size_t)(a0 + row) << 5)) + half * 4;
        const float4* xb = (const float4*)(x + ((size_t)(b0 + row) << 5)) + half * 4;
        float sa = cvt_store(Abuf, row,   half, xa);
        float sb = cvt_store(Bbuf, srowB, half, xb);
        sa += __shfl_xor_sync(0xFFFFFFFFu, sa, 1);
        sb += __shfl_xor_sync(0xFFFFFFFFu, sb, 1);
        if (!half) { sqa[row] = sa; sqb[row] = sb; }
    }
    __syncthreads();

    // ---- warp GEMM: warp tile 64x32, 2x4 warp grid ----
    const int wr = wid >> 2;
    const int wc = wid & 3;

    // A: ldmatrix.x4 per m-tile; rows wr*64+mt*16+(lane&15), k-half by lane>=16
    const uint32_t aBase  = smem_u32(Abuf) + (uint32_t)(wr * 64 + (lane & 15)) * 128;
    const uint32_t aKhalf = (uint32_t)(lane >> 4) << 4;
    const uint32_t xmask  = (uint32_t)(lane & 7) << 4;
    // B: ldmatrix.x4 per n-tile-PAIR; rows wc*32+16u+((lane>>4)<<3)+(lane&7)
    const uint32_t bBase  = smem_u32(Bbuf) +
        (uint32_t)(wc * 32 + ((lane >> 4) << 3) + (lane & 7)) * 128;
    const uint32_t bKhalf = (uint32_t)((lane >> 3) & 1) << 4;

    float acc[4][4][4];
#pragma unroll
    for (int mt = 0; mt < 4; mt++)
#pragma unroll
        for (int nt = 0; nt < 4; nt++)
#pragma unroll
            for (int i = 0; i < 4; i++) acc[mt][nt][i] = 0.0f;

#pragma unroll
    for (int ks = 0; ks < 2; ks++) {
        const uint32_t ahOff = (uint32_t)(ks * 32) + aKhalf;        // hi bytes 0/32
        const uint32_t bhOff = (uint32_t)(ks * 32) + bKhalf;
        uint32_t ah[4][4], al[4][4], bh[2][4], bl[2][4];

#pragma unroll
        for (int mt = 0; mt < 4; mt++)
            ldmatrix_x4(ah[mt], aBase + (uint32_t)mt * 2048 + (ahOff ^ xmask));
#pragma unroll
        for (int u = 0; u < 2; u++)
            ldmatrix_x4(bh[u], bBase + (uint32_t)u * 2048 + (bhOff ^ xmask));
        // hi . hi
#pragma unroll
        for (int mt = 0; mt < 4; mt++)
#pragma unroll
            for (int nt = 0; nt < 4; nt++)
                mma_bf16(acc[mt][nt], ah[mt], &bh[nt >> 1][(nt & 1) * 2]);

#pragma unroll
        for (int u = 0; u < 2; u++)
            ldmatrix_x4(bl[u], bBase + (uint32_t)u * 2048 + ((bhOff + 64) ^ xmask));
        // hi . lo
#pragma unroll
        for (int mt = 0; mt < 4; mt++)
#pragma unroll
            for (int nt = 0; nt < 4; nt++)
                mma_bf16(acc[mt][nt], ah[mt], &bl[nt >> 1][(nt & 1) * 2]);

#pragma unroll
        for (int mt = 0; mt < 4; mt++)
            ldmatrix_x4(al[mt], aBase + (uint32_t)mt * 2048 + ((ahOff + 64) ^ xmask));
        // lo . hi
#pragma unroll
        for (int mt = 0; mt < 4; mt++)
#pragma unroll
            for (int nt = 0; nt < 4; nt++)
                mma_bf16(acc[mt][nt], al[mt], &bh[nt >> 1][(nt & 1) * 2]);
    }

    // ---- epilogue: STG.128, 4 contiguous global cols per thread ----
    const int q  = lane & 3;
    const int gr = lane >> 2;
    const bool diag = (a0 == b0);
#pragma unroll
    for (int mt = 0; mt < 4; mt++) {
        const int r0l = wr * 64 + mt * 16 + gr;
        const int r1l = r0l + 8;
        const float si0 = sqa[r0l], si1 = sqa[r1l];
        const int g0 = a0 + r0l, g1 = a0 + r1l;
        float* __restrict__ o0 = out + ((size_t)g0 << 14);
        float* __restrict__ o1 = out + ((size_t)g1 << 14);
#pragma unroll
        for (int u = 0; u < 2; u++) {
            const int cl = wc * 32 + u * 16 + q * 4;   // global col (tile-local)
            const int gc = b0 + cl;
            const float4 sj = *(const float4*)&sqb[cl];
            const float* a0p = acc[mt][2 * u];       // smem cols 2q,2q+1 -> g 4q,4q+1
            const float* a1p = acc[mt][2 * u + 1];   // smem cols 8+2q,+1 -> g 4q+2,4q+3
            float4 w0, w1;
            w0.x = dist_val(si0, sj.x, a0p[0]);
            w0.y = dist_val(si0, sj.y, a0p[1]);
            w0.z = dist_val(si0, sj.z, a1p[0]);
            w0.w = dist_val(si0, sj.w, a1p[1]);
            w1.x = dist_val(si1, sj.x, a0p[2]);
            w1.y = dist_val(si1, sj.y, a0p[3]);
            w1.z = dist_val(si1, sj.z, a1p[2]);
            w1.w = dist_val(si1, sj.w, a1p[3]);
            if (diag) {
                int d0 = g0 - gc;
                if (d0 >= 0 && d0 < 4) ((float*)&w0)[d0] = 0.0f;
                int d1 = g1 - gc;
                if (d1 >= 0 && d1 < 4) ((float*)&w1)[d1] = 0.0f;
            }
            *(float4*)(o0 + gc) = w0;
            *(float4*)(o1 + gc) = w1;
        }
    }
}

extern "C" void kernel_launch(void* const* d_in, const int* in_sizes, int n_in,
                              void* d_out, int out_size)
{
    (void)in_sizes; (void)n_in; (void)out_size;
    const float* x = (const float*)d_in[0];
    float* out = (float*)d_out;
    dim3 grid(NPTS / 128, NPTS / 128);
    dim3 block(256);
    cdist_mma_kernel<<<grid, block>>>(x, out);
}